// round 17
// baseline (speedup 1.0000x reference)
#include <cuda_runtime.h>
#include <cuda_bf16.h>
#include <math.h>

// 4-qubit circuit: RY(x) encoding + 6 BasicEntangler layers -> <Z_q>.
// out_q(x) = sum_{t0,t1} g0 g1 * [ sum_{t2} g2 * (c0 + C3 c1 + S3 c2) ],
// g = (1, cos x_q, sin x_q).
// f32x2 lanes carry OUTPUT PAIRS (q0,q1)/(q2,q3) for one sample (trig
// duplicated per-lane). Coefficients are NON-duplicated in plain GLOBAL
// memory, read as 3 uniform LDG.128 per t012 — generic loads cannot be
// hoisted above cudaGridDependencySynchronize() (the R15 failure was
// __constant__ loads hoisted above the PDL sync, reading pre-setup zeros).

#define NQ 4
#define NL 6
#define SPACK 4            // 4 samples per thread
#define TPB 128

// [t][q] non-duplicated, t = t012*3 + t3, 324 floats.
__device__ __align__(16) float g_coef[324];

// ---------------------------------------------------------------------------
// f32x2 packed helpers (PTX-only on Blackwell; ptxas won't auto-fuse)
// ---------------------------------------------------------------------------
__device__ __forceinline__ unsigned long long pk2(float lo, float hi) {
    unsigned long long r;
    asm("mov.b64 %0, {%1, %2};" : "=l"(r) : "f"(lo), "f"(hi));
    return r;
}
__device__ __forceinline__ void upk2(unsigned long long v, float& lo, float& hi) {
    asm("mov.b64 {%0, %1}, %2;" : "=f"(lo), "=f"(hi) : "l"(v));
}
__device__ __forceinline__ unsigned long long mul2(unsigned long long a, unsigned long long b) {
    unsigned long long d;
    asm("mul.rn.f32x2 %0, %1, %2;" : "=l"(d) : "l"(a), "l"(b));
    return d;
}
__device__ __forceinline__ unsigned long long fma2(unsigned long long a, unsigned long long b,
                                                   unsigned long long c) {
    unsigned long long d;
    asm("fma.rn.f32x2 %0, %1, %2, %3;" : "=l"(d) : "l"(a), "l"(b), "l"(c));
    return d;
}

// ---------------------------------------------------------------------------
// Setup: simulate the 16x16 entangler unitary, build S_q = Re(U^dag Z_q U),
// factored mode-transform, emit non-duplicated [t][q] coefficient table.
// PDL trigger fires FIRST so the eval grid launches concurrently.
// ---------------------------------------------------------------------------
__global__ void setup_kernel(const float* __restrict__ w, float* coef_out) {
    cudaTriggerProgrammaticLaunchCompletion();

    __shared__ float sct[NL * NQ];
    __shared__ float sst[NL * NQ];
    __shared__ float Ure[16][16];
    __shared__ float Uim[16][16];
    __shared__ float Sq[1024];
    __shared__ float bufA[768];
    __shared__ float bufB[576];

    int tid = threadIdx.x;

    if (tid < NL * NQ) {
        float t = 0.5f * w[tid];
        float ct, st;
        __sincosf(t, &st, &ct);
        sct[tid] = ct;
        sst[tid] = st;
    }
    __syncthreads();

    if (tid < 16) {
        float re[16], im[16];
        #pragma unroll
        for (int b = 0; b < 16; b++) { re[b] = 0.0f; im[b] = 0.0f; }
        re[tid] = 1.0f;

        #pragma unroll 1
        for (int l = 0; l < NL; l++) {
            #pragma unroll
            for (int q = 0; q < 4; q++) {
                float ct = sct[l * 4 + q];
                float st = sst[l * 4 + q];
                int mask = 8 >> q;   // qubit 0 = MSB
                #pragma unroll
                for (int b = 0; b < 16; b++) {
                    if (b & mask) continue;
                    int p = b | mask;
                    float r0 = re[b], i0 = im[b], r1 = re[p], i1 = im[p];
                    re[b] = ct * r0 + st * i1;
                    im[b] = ct * i0 - st * r1;
                    re[p] = ct * r1 + st * i0;
                    im[p] = ct * i1 - st * r0;
                }
            }
            #pragma unroll
            for (int q = 0; q < 4; q++) {
                int cm = 8 >> q;
                int tm = 8 >> ((q + 1) & 3);
                #pragma unroll
                for (int b = 0; b < 16; b++) {
                    if (!(b & cm)) continue;
                    if (b & tm) continue;
                    int p = b | tm;
                    float tr = re[b]; re[b] = re[p]; re[p] = tr;
                    float ti = im[b]; im[b] = im[p]; im[p] = ti;
                }
            }
        }
        #pragma unroll
        for (int b = 0; b < 16; b++) { Ure[b][tid] = re[b]; Uim[b][tid] = im[b]; }
    }
    __syncthreads();

    for (int e = tid; e < 1024; e += blockDim.x) {
        int q = e >> 8;
        int i = (e >> 4) & 15;
        int j = e & 15;
        int mask = 8 >> q;
        float s = 0.0f;
        #pragma unroll
        for (int b = 0; b < 16; b++) {
            float zz = (b & mask) ? -1.0f : 1.0f;
            s += zz * (Ure[b][i] * Ure[b][j] + Uim[b][i] * Uim[b][j]);
        }
        Sq[e] = s;
    }
    __syncthreads();

    // Stage s contracts qubit-s pair index (i_s, j_s) -> t_s in basis (1, C, S):
    //   t=0: (S00+S11)/2 ; t=1: (S00-S11)/2 ; t=2: (S01+S10)/2
    const int pow3[4] = {1, 3, 9, 27};
    const float* in = Sq;
    float* out = bufA;
    for (int s = 0; s < 4; s++) {
        int R = 8 >> s;
        int T = pow3[s];
        int D = 2 * R;
        int outN = 4 * T * 3 * R * R;
        for (int e = tid; e < outN; e += blockDim.x) {
            int j2 = e % R;
            int i2 = (e / R) % R;
            int t  = (e / (R * R)) % 3;
            int tp = (e / (R * R * 3)) % T;
            int q  = e / (R * R * 3 * T);
            const float* base = in + (q * T + tp) * D * D;
            float v;
            if (t == 0)      v = 0.5f * (base[i2 * D + j2] + base[(i2 + R) * D + (j2 + R)]);
            else if (t == 1) v = 0.5f * (base[i2 * D + j2] - base[(i2 + R) * D + (j2 + R)]);
            else             v = 0.5f * (base[i2 * D + j2 + R] + base[(i2 + R) * D + j2]);
            out[(((q * T + tp) * 3 + t) * R + i2) * R + j2] = v;
        }
        __syncthreads();
        in = out;
        out = (out == bufA) ? bufB : bufA;
    }
    // in[] = [q][t], t = t0*27 + t1*9 + t2*3 + t3. Emit [t][q] non-duplicated.
    for (int e = tid; e < 324; e += blockDim.x) {
        int q = e / 81;
        int t = e % 81;
        coef_out[t * 4 + q] = in[e];
    }
}

// ---------------------------------------------------------------------------
// Eval: 4 samples per thread; each f32x2 carries (q0,q1) or (q2,q3) for one
// sample. Coefficients via generic global loads (3x uniform LDG.128 / t012),
// correctly ordered after the PDL grid-dependency sync.
// ---------------------------------------------------------------------------
__global__ void __launch_bounds__(TPB, 3) eval_kernel(const float4* __restrict__ x,
                                                      float4* __restrict__ out,
                                                      const float* gc,
                                                      int nB) {
    const int base = blockIdx.x * (SPACK * TPB) + threadIdx.x;

    unsigned long long C0[SPACK], S0[SPACK], C1[SPACK], S1[SPACK];
    unsigned long long C2[SPACK], S2[SPACK], C3[SPACK], S3[SPACK];
    int idx[SPACK];

    #pragma unroll
    for (int s = 0; s < SPACK; s++) {
        idx[s] = base + s * TPB;
        float4 xv = (idx[s] < nB) ? x[idx[s]] : make_float4(0.f, 0.f, 0.f, 0.f);
        float c0, s0, c1, s1, c2, s2, c3, s3;
        __sincosf(xv.x, &s0, &c0);
        __sincosf(xv.y, &s1, &c1);
        __sincosf(xv.z, &s2, &c2);
        __sincosf(xv.w, &s3, &c3);
        C0[s] = pk2(c0, c0);  S0[s] = pk2(s0, s0);
        C1[s] = pk2(c1, c1);  S1[s] = pk2(s1, s1);
        C2[s] = pk2(c2, c2);  S2[s] = pk2(s2, s2);
        C3[s] = pk2(c3, c3);  S3[s] = pk2(s3, s3);
    }

    // Wait for the producer (setup) grid's writes before reading coefficients.
    cudaGridDependencySynchronize();

    unsigned long long accA[SPACK];   // (out0, out1)
    unsigned long long accB[SPACK];   // (out2, out3)

    #pragma unroll
    for (int t0 = 0; t0 < 3; t0++) {
        #pragma unroll
        for (int t1 = 0; t1 < 3; t1++) {
            const int a = t0 * 3 + t1;
            unsigned long long u[SPACK];
            if (a != 0) {
                #pragma unroll
                for (int s = 0; s < SPACK; s++) {
                    if (t0 == 0)      u[s] = (t1 == 1) ? C1[s] : S1[s];
                    else if (t1 == 0) u[s] = (t0 == 1) ? C0[s] : S0[s];
                    else {
                        unsigned long long e0 = (t0 == 1) ? C0[s] : S0[s];
                        unsigned long long e1 = (t1 == 1) ? C1[s] : S1[s];
                        u[s] = mul2(e0, e1);
                    }
                }
            }

            unsigned long long v2A[SPACK], v2B[SPACK];
            #pragma unroll
            for (int t2 = 0; t2 < 3; t2++) {
                const int t012 = a * 3 + t2;
                // 12 floats per t012: rows t3=0,1,2, each (q0,q1,q2,q3).
                const ulonglong2* gp = (const ulonglong2*)(gc + t012 * 12);
                ulonglong2 r0 = gp[0];   // t3=0: (q0q1, q2q3)
                ulonglong2 r1 = gp[1];   // t3=1
                ulonglong2 r2 = gp[2];   // t3=2
                #pragma unroll
                for (int s = 0; s < SPACK; s++) {
                    unsigned long long vA = fma2(C3[s], r1.x, r0.x);
                    vA = fma2(S3[s], r2.x, vA);
                    unsigned long long vB = fma2(C3[s], r1.y, r0.y);
                    vB = fma2(S3[s], r2.y, vB);
                    if (t2 == 0)      { v2A[s] = vA;                        v2B[s] = vB; }
                    else if (t2 == 1) { v2A[s] = fma2(C2[s], vA, v2A[s]);   v2B[s] = fma2(C2[s], vB, v2B[s]); }
                    else              { v2A[s] = fma2(S2[s], vA, v2A[s]);   v2B[s] = fma2(S2[s], vB, v2B[s]); }
                }
            }

            #pragma unroll
            for (int s = 0; s < SPACK; s++) {
                if (a == 0) { accA[s] = v2A[s];                      accB[s] = v2B[s]; }
                else        { accA[s] = fma2(u[s], v2A[s], accA[s]); accB[s] = fma2(u[s], v2B[s], accB[s]); }
            }
        }
    }

    #pragma unroll
    for (int s = 0; s < SPACK; s++) {
        float o0, o1, o2, o3;
        upk2(accA[s], o0, o1);
        upk2(accB[s], o2, o3);
        if (idx[s] < nB) out[idx[s]] = make_float4(o0, o1, o2, o3);
    }
}

extern "C" void kernel_launch(void* const* d_in, const int* in_sizes, int n_in,
                              void* d_out, int out_size) {
    const float* x = (const float*)d_in[0];
    const float* w = (const float*)d_in[1];
    int nx = in_sizes[0];
    if (in_sizes[0] == NL * NQ && n_in > 1) {   // swapped order safety
        x = (const float*)d_in[1];
        w = (const float*)d_in[0];
        nx = in_sizes[1];
    }
    int B = nx / 4;

    void* coef_dev = nullptr;
    cudaGetSymbolAddress(&coef_dev, g_coef);

    setup_kernel<<<1, 256>>>(w, (float*)coef_dev);

    int samplesPerBlock = SPACK * TPB;   // 512
    int blocks = (B + samplesPerBlock - 1) / samplesPerBlock;

    // PDL launch: eval starts while setup runs (setup triggers at entry);
    // the in-kernel cudaGridDependencySynchronize() provides the ordering.
    cudaLaunchConfig_t cfg = {};
    cfg.gridDim = dim3((unsigned)blocks);
    cfg.blockDim = dim3(TPB);
    cfg.dynamicSmemBytes = 0;
    cfg.stream = 0;
    cudaLaunchAttribute attrs[1];
    attrs[0].id = cudaLaunchAttributeProgrammaticStreamSerialization;
    attrs[0].val.programmaticStreamSerializationAllowed = 1;
    cfg.attrs = attrs;
    cfg.numAttrs = 1;
    cudaError_t err = cudaLaunchKernelEx(&cfg, eval_kernel,
                                         (const float4*)x, (float4*)d_out,
                                         (const float*)coef_dev, B);
    if (err != cudaSuccess) {
        eval_kernel<<<blocks, TPB>>>((const float4*)x, (float4*)d_out,
                                     (const float*)coef_dev, B);
    }
}